// round 1
// baseline (speedup 1.0000x reference)
#include <cuda_runtime.h>
#include <math.h>

#define SS 2048
#define NN 32
#define HH 1024
#define EE 1024
#define MM (SS*NN)   // 65536 rows

#define BM 128
#define BN 64
#define BK 16

// ---- scratch (static __device__: no allocation in kernel_launch) ----
__device__ float g_u[NN*EE];        // u[n][e] = hidden_d[n]·W1[e] + b1[e] + b2[e]
__device__ float g_a[NN*SS];        // logits, transposed [n][s]
__device__ float g_alpha[NN*SS];    // softmax, transposed [n][s]
__device__ float g_cpart[32*NN*HH]; // partial context sums over 32 s-chunks

// ---- f32x2 helpers (FFMA2 path; 2x fp32 throughput vs scalar FFMA on sm_103a) ----
__device__ __forceinline__ unsigned long long pack2same(float v) {
    unsigned long long r; unsigned u = __float_as_uint(v);
    asm("mov.b64 %0, {%1, %1};" : "=l"(r) : "r"(u));
    return r;
}
__device__ __forceinline__ unsigned long long ffma2(unsigned long long a,
                                                    unsigned long long b,
                                                    unsigned long long c) {
    unsigned long long d;
    asm("fma.rn.f32x2 %0, %1, %2, %3;" : "=l"(d) : "l"(a), "l"(b), "l"(c));
    return d;
}
__device__ __forceinline__ float2 unpack2(unsigned long long v) {
    unsigned lo, hi;
    asm("mov.b64 {%0, %1}, %2;" : "=r"(lo), "=r"(hi) : "l"(v));
    float2 r; r.x = __uint_as_float(lo); r.y = __uint_as_float(hi);
    return r;
}

// ============================================================================
// Kernel 1: u[n][e] = hidden_d[n]·W1[e] + b1[e] + b2[e]   (one warp per dot)
// ============================================================================
__global__ void k_u(const float* __restrict__ hidden, const float* __restrict__ W1,
                    const float* __restrict__ b1, const float* __restrict__ b2) {
    int gw = (blockIdx.x * blockDim.x + threadIdx.x) >> 5;
    int lane = threadIdx.x & 31;
    if (gw >= NN * EE) return;
    int n = gw >> 10;          // / EE
    int e = gw & (EE - 1);
    const float* hv = hidden + n * HH;
    const float* wv = W1 + (size_t)e * HH;
    float s = 0.f;
    #pragma unroll 4
    for (int h = lane; h < HH; h += 32) s = fmaf(hv[h], wv[h], s);
    #pragma unroll
    for (int o = 16; o; o >>= 1) s += __shfl_down_sync(0xffffffffu, s, o);
    if (lane == 0) g_u[n * EE + e] = s + b1[e] + b2[e];
}

// ============================================================================
// Kernel 2: fused  y = X·W2ᵀ  ->  +u  ->  tanh  ->  ·W3 row-reduce  ->  a[m]
//   X = out_e viewed as (M=S*N, H). Block: 128 rows x 64 e-cols tile, loops
//   over all 16 column tiles so each row's a is produced by exactly one block
//   in a fixed order (deterministic, no atomics).
// ============================================================================
__global__ void __launch_bounds__(256, 2)
k_main(const float* __restrict__ X, const float* __restrict__ W2,
       const float* __restrict__ W3, const float* __restrict__ b3) {
    __shared__ float As[BK][BM + 4];   // [k][row]
    __shared__ float Bs[BK][BN + 4];   // [k][e_local]
    __shared__ float sW3[EE];
    __shared__ float red[BM][17];

    const int tid = threadIdx.x;
    const int m0  = blockIdx.x * BM;
    const int rg  = tid >> 4;          // 0..15 row group
    const int cg  = tid & 15;          // 0..15 col group
    const int r0  = rg * 8;
    const int c0  = cg * 4;

    for (int i = tid; i < EE; i += 256) sW3[i] = W3[i];

    float pa[8];
    #pragma unroll
    for (int i = 0; i < 8; i++) pa[i] = 0.f;

    for (int ct = 0; ct < EE / BN; ++ct) {
        unsigned long long acc[4][4];
        #pragma unroll
        for (int rp = 0; rp < 4; rp++)
            #pragma unroll
            for (int j = 0; j < 4; j++) acc[rp][j] = 0ull;

        for (int kk = 0; kk < HH; kk += BK) {
            // load X tile: 128 rows x 16 k (2 float4 per thread)
            #pragma unroll
            for (int t = 0; t < 2; t++) {
                int ff  = tid + t * 256;
                int row = ff >> 2;
                int kq  = ff & 3;
                float4 v = *(const float4*)(X + (size_t)(m0 + row) * HH + kk + kq * 4);
                As[kq * 4 + 0][row] = v.x;
                As[kq * 4 + 1][row] = v.y;
                As[kq * 4 + 2][row] = v.z;
                As[kq * 4 + 3][row] = v.w;
            }
            // load W2 tile: 64 e-rows x 16 k (1 float4 per thread)
            {
                int row = tid >> 2;
                int kq  = tid & 3;
                float4 v = *(const float4*)(W2 + (size_t)(ct * BN + row) * HH + kk + kq * 4);
                Bs[kq * 4 + 0][row] = v.x;
                Bs[kq * 4 + 1][row] = v.y;
                Bs[kq * 4 + 2][row] = v.z;
                Bs[kq * 4 + 3][row] = v.w;
            }
            __syncthreads();

            #pragma unroll
            for (int k = 0; k < BK; k++) {
                unsigned long long arow[4];
                #pragma unroll
                for (int rp = 0; rp < 4; rp++)
                    arow[rp] = *(const unsigned long long*)&As[k][r0 + 2 * rp];
                float4 bv = *(const float4*)&Bs[k][c0];
                unsigned long long bb0 = pack2same(bv.x);
                unsigned long long bb1 = pack2same(bv.y);
                unsigned long long bb2 = pack2same(bv.z);
                unsigned long long bb3 = pack2same(bv.w);
                #pragma unroll
                for (int rp = 0; rp < 4; rp++) {
                    acc[rp][0] = ffma2(arow[rp], bb0, acc[rp][0]);
                    acc[rp][1] = ffma2(arow[rp], bb1, acc[rp][1]);
                    acc[rp][2] = ffma2(arow[rp], bb2, acc[rp][2]);
                    acc[rp][3] = ffma2(arow[rp], bb3, acc[rp][3]);
                }
            }
            __syncthreads();
        }

        // epilogue for this column tile: +u, tanh, *W3, accumulate into pa
        #pragma unroll
        for (int rp = 0; rp < 4; rp++) {
            int m_lo = m0 + r0 + 2 * rp;
            int n_lo = m_lo & (NN - 1);
            int n_hi = (m_lo + 1) & (NN - 1);
            #pragma unroll
            for (int j = 0; j < 4; j++) {
                int e = ct * BN + c0 + j;
                float2 z = unpack2(acc[rp][j]);
                float w3 = sW3[e];
                float zl = z.x + g_u[n_lo * EE + e];
                float zh = z.y + g_u[n_hi * EE + e];
                pa[2 * rp]     = fmaf(tanhf(zl), w3, pa[2 * rp]);
                pa[2 * rp + 1] = fmaf(tanhf(zh), w3, pa[2 * rp + 1]);
            }
        }
    }

    // reduce pa across the 16 column groups for each of the 128 rows
    #pragma unroll
    for (int i = 0; i < 8; i++) red[r0 + i][cg] = pa[i];
    __syncthreads();
    if (tid < BM) {
        float s = 0.f;
        #pragma unroll
        for (int c = 0; c < 16; c++) s += red[tid][c];
        int m = m0 + tid;
        int n = m & (NN - 1);
        int srcpos = m >> 5;          // m / NN
        g_a[n * SS + srcpos] = s + b3[0];
    }
}

// ============================================================================
// Kernel 3: softmax over S per column n. Writes g_alpha and (optionally) the
// alpha section of d_out in reference layout alpha[s*N + n].
// ============================================================================
__global__ void k_softmax(float* __restrict__ alpha_out, int write_out) {
    int n = blockIdx.x;
    int tid = threadIdx.x;
    __shared__ float sred[256];
    const float* av = g_a + n * SS;

    float vals[8];
    float mx = -1e30f;
    #pragma unroll
    for (int i = 0; i < 8; i++) { vals[i] = av[tid + i * 256]; mx = fmaxf(mx, vals[i]); }
    sred[tid] = mx; __syncthreads();
    for (int o = 128; o; o >>= 1) { if (tid < o) sred[tid] = fmaxf(sred[tid], sred[tid + o]); __syncthreads(); }
    mx = sred[0]; __syncthreads();

    float lsum = 0.f;
    #pragma unroll
    for (int i = 0; i < 8; i++) { vals[i] = __expf(vals[i] - mx); lsum += vals[i]; }
    sred[tid] = lsum; __syncthreads();
    for (int o = 128; o; o >>= 1) { if (tid < o) sred[tid] += sred[tid + o]; __syncthreads(); }
    float inv = 1.f / sred[0];

    #pragma unroll
    for (int i = 0; i < 8; i++) {
        int s = tid + i * 256;
        float al = vals[i] * inv;
        g_alpha[n * SS + s] = al;
        if (write_out) alpha_out[s * NN + n] = al;
    }
}

// ============================================================================
// Kernel 4/5: context c[n][h] = sum_s alpha[s,n]*out_e[s,n,h]
//   Deterministic two-stage: 32 fixed s-chunks -> partials -> fixed-order sum.
// ============================================================================
__global__ void k_cpart(const float* __restrict__ X) {
    int chunk = blockIdx.x;   // 0..31
    int n     = blockIdx.y;   // 0..31
    int h0    = threadIdx.x * 4;
    float4 acc = make_float4(0.f, 0.f, 0.f, 0.f);
    int sbeg = chunk * (SS / 32);
    for (int s = sbeg; s < sbeg + (SS / 32); ++s) {
        float al = g_alpha[n * SS + s];
        float4 v = *(const float4*)(X + (size_t)(s * NN + n) * HH + h0);
        acc.x = fmaf(al, v.x, acc.x);
        acc.y = fmaf(al, v.y, acc.y);
        acc.z = fmaf(al, v.z, acc.z);
        acc.w = fmaf(al, v.w, acc.w);
    }
    *(float4*)(g_cpart + ((size_t)(chunk * NN + n) * HH) + h0) = acc;
}

__global__ void k_cfinal(float* __restrict__ cout) {
    int idx = blockIdx.x * 256 + threadIdx.x;   // 0 .. N*H-1
    float s = 0.f;
    #pragma unroll
    for (int ch = 0; ch < 32; ++ch) s += g_cpart[(size_t)ch * NN * HH + idx];
    cout[idx] = s;
}

// ============================================================================
extern "C" void kernel_launch(void* const* d_in, const int* in_sizes, int n_in,
                              void* d_out, int out_size) {
    const float* out_e  = (const float*)d_in[0];
    const float* hidden = (const float*)d_in[1];
    const float* W1     = (const float*)d_in[2];
    const float* b1     = (const float*)d_in[3];
    const float* W2     = (const float*)d_in[4];
    const float* b2     = (const float*)d_in[5];
    const float* W3     = (const float*)d_in[6];
    const float* b3     = (const float*)d_in[7];
    float* outp = (float*)d_out;

    // u precompute: one warp per (n,e) dot product
    k_u<<<(NN * EE) / 8, 256>>>(hidden, W1, b1, b2);

    // fused GEMM + tanh + W3 reduction -> logits
    k_main<<<MM / BM, 256>>>(out_e, W2, W3, b3);

    // output layout: (c, alpha) tuple flattened -> c first, then alpha.
    int has_both  = (out_size >= NN * HH + SS * NN);
    int alpha_only = (!has_both && out_size == SS * NN);
    float* alpha_dst = has_both ? (outp + NN * HH) : (alpha_only ? outp : nullptr);

    k_softmax<<<NN, 256>>>(alpha_dst, alpha_dst != nullptr);

    if (!alpha_only) {
        dim3 g(32, NN);
        k_cpart<<<g, 256>>>(out_e);
        k_cfinal<<<(NN * HH) / 256, 256>>>(outp);
    }
}

// round 3
// speedup vs baseline: 2.7426x; 2.7426x over previous
#include <cuda_runtime.h>
#include <math.h>
#include <stdint.h>

#define SS 2048
#define NN 32
#define HH 1024
#define EE 1024
#define MM (SS*NN)   // 65536 rows

// ---- scratch (static __device__: no allocation in kernel_launch) ----
__device__ float g_u[NN*EE];        // u[n][e] = hidden_d[n]·W1[e] + b1[e] + b2[e]
__device__ float g_a[NN*SS];        // logits, transposed [n][s]
__device__ float g_alpha[NN*SS];    // softmax, transposed [n][s]
__device__ float g_cpart[32*NN*HH]; // partial context sums over 32 s-chunks

// ============================================================================
// PTX helpers (all target-portable: sm_80+ features only)
// ============================================================================
__device__ __forceinline__ uint32_t smem_u32(const void* p) {
    uint32_t a;
    asm("{ .reg .u64 t; cvta.to.shared.u64 t, %1; cvt.u32.u64 %0, t; }" : "=r"(a) : "l"(p));
    return a;
}
#define CP_ASYNC16(dst, src) \
    asm volatile("cp.async.cg.shared.global [%0], [%1], 16;" :: "r"(dst), "l"(src) : "memory")
#define CP_COMMIT() asm volatile("cp.async.commit_group;" ::: "memory")
#define CP_WAIT1()  asm volatile("cp.async.wait_group 1;" ::: "memory")
#define CP_WAIT0()  asm volatile("cp.async.wait_group 0;" ::: "memory")

__device__ __forceinline__ uint32_t f2tf32(float x) {
    uint32_t r;
    asm("cvt.rna.tf32.f32 %0, %1;" : "=r"(r) : "f"(x));
    return r;
}
__device__ __forceinline__ void mma_tf32(float c[4],
                                         uint32_t a0, uint32_t a1, uint32_t a2, uint32_t a3,
                                         uint32_t b0, uint32_t b1) {
    asm volatile(
        "mma.sync.aligned.m16n8k8.row.col.f32.tf32.tf32.f32 "
        "{%0,%1,%2,%3}, {%4,%5,%6,%7}, {%8,%9}, {%0,%1,%2,%3};"
        : "+f"(c[0]), "+f"(c[1]), "+f"(c[2]), "+f"(c[3])
        : "r"(a0), "r"(a1), "r"(a2), "r"(a3), "r"(b0), "r"(b1));
}

// ============================================================================
// Kernel 1: u[n][e] = hidden_d[n]·W1[e] + b1[e] + b2[e]   (one warp per dot)
// ============================================================================
__global__ void k_u(const float* __restrict__ hidden, const float* __restrict__ W1,
                    const float* __restrict__ b1, const float* __restrict__ b2) {
    int gw = (blockIdx.x * blockDim.x + threadIdx.x) >> 5;
    int lane = threadIdx.x & 31;
    if (gw >= NN * EE) return;
    int n = gw >> 10;
    int e = gw & (EE - 1);
    const float* hv = hidden + n * HH;
    const float* wv = W1 + (size_t)e * HH;
    float s = 0.f;
    #pragma unroll 4
    for (int h = lane; h < HH; h += 32) s = fmaf(hv[h], wv[h], s);
    #pragma unroll
    for (int o = 16; o; o >>= 1) s += __shfl_down_sync(0xffffffffu, s, o);
    if (lane == 0) g_u[n * EE + e] = s + b1[e] + b2[e];
}

// ============================================================================
// Kernel 2: mma.sync tf32 fused  X·W2ᵀ -> +u -> tanh -> ·W3 row-reduce -> a[m]
//   Block: 128 rows x full E (8 n-tiles of 128). 256 thr = 8 warps.
//   Warp tile 32x64: warp_m = wid&3 (4x32 rows), warp_n = wid>>2 (2x64 cols).
//   K pipeline: 32-float chunks, 3 smem buffers, cp.async.
// ============================================================================
#define NSTG 256          // 8 n-tiles * 32 k-chunks
#define ASTRIDE 36        // 32 + 4 pad: conflict-free fragment LDS
#define SU_STRIDE 132

__global__ void __launch_bounds__(256, 1)
k_gemm(const float* __restrict__ X, const float* __restrict__ W2,
       const float* __restrict__ W3, const float* __restrict__ b3) {
    extern __shared__ float sm[];
    float* As  = sm;                        // 3*128*36 = 13824
    float* Bs  = As + 3 * 128 * ASTRIDE;    // 13824
    float* su  = Bs + 3 * 128 * ASTRIDE;    // 32*132 = 4224
    float* red = su + 32 * SU_STRIDE;       // 128*2

    const int tid = threadIdx.x;
    const int wid = tid >> 5;
    const int lid = tid & 31;
    const int g   = lid >> 2;          // fragment group 0..7
    const int tg  = lid & 3;           // thread-in-group 0..3
    const int warp_m = wid & 3;
    const int warp_n = wid >> 2;
    const int mbase = warp_m * 32;
    const int nbase = warp_n * 64;
    const int m0 = blockIdx.x * 128;

    const uint32_t sA = smem_u32(As);
    const uint32_t sB = smem_u32(Bs);

    // per-thread load coords: 8 x 16B chunks per 32-float row
    const int l_ch  = tid & 7;         // chunk 0..7
    const int l_row = tid >> 3;        // 0..31 (x4 passes -> 128 rows)

    auto do_load = [&](int ls) {
        int nt  = ls >> 5;
        int kc  = ls & 31;
        int buf = ls - (ls / 3) * 3;
        const float* gA = X  + (size_t)(m0 + l_row) * HH + kc * 32 + l_ch * 4;
        const float* gB = W2 + (size_t)(nt * 128 + l_row) * HH + kc * 32 + l_ch * 4;
        uint32_t dA = sA + ((buf * 128 + l_row) * ASTRIDE + l_ch * 4) * 4;
        uint32_t dB = sB + ((buf * 128 + l_row) * ASTRIDE + l_ch * 4) * 4;
        #pragma unroll
        for (int t = 0; t < 4; t++) {
            CP_ASYNC16(dA, gA);
            CP_ASYNC16(dB, gB);
            gA += 32 * HH; gB += 32 * HH;
            dA += 32 * ASTRIDE * 4; dB += 32 * ASTRIDE * 4;
        }
        CP_COMMIT();
    };

    float acc[2][8][4];
    #pragma unroll
    for (int i = 0; i < 2; i++)
        #pragma unroll
        for (int j = 0; j < 8; j++)
            #pragma unroll
            for (int q = 0; q < 4; q++) acc[i][j][q] = 0.f;
    float pa[4] = {0.f, 0.f, 0.f, 0.f};

    do_load(0);
    do_load(1);

    for (int ls = 0; ls < NSTG; ++ls) {
        int kc  = ls & 31;
        int nt  = ls >> 5;
        int buf = ls - (ls / 3) * 3;

        if (ls < NSTG - 1) { CP_WAIT1(); } else { CP_WAIT0(); }
        __syncthreads();

        const float* Ab = As + buf * 128 * ASTRIDE;
        const float* Bb = Bs + buf * 128 * ASTRIDE;

        #pragma unroll
        for (int q = 0; q < 4; q++) {
            const int k0 = q * 8;
            uint32_t af[2][4];
            #pragma unroll
            for (int i = 0; i < 2; i++) {
                int r = mbase + i * 16 + g;
                af[i][0] = f2tf32(Ab[r * ASTRIDE + k0 + tg]);
                af[i][1] = f2tf32(Ab[(r + 8) * ASTRIDE + k0 + tg]);
                af[i][2] = f2tf32(Ab[r * ASTRIDE + k0 + tg + 4]);
                af[i][3] = f2tf32(Ab[(r + 8) * ASTRIDE + k0 + tg + 4]);
            }
            #pragma unroll
            for (int j = 0; j < 8; j++) {
                int cl = nbase + j * 8 + g;
                uint32_t b0 = f2tf32(Bb[cl * ASTRIDE + k0 + tg]);
                uint32_t b1 = f2tf32(Bb[cl * ASTRIDE + k0 + tg + 4]);
                mma_tf32(acc[0][j], af[0][0], af[0][1], af[0][2], af[0][3], b0, b1);
                mma_tf32(acc[1][j], af[1][0], af[1][1], af[1][2], af[1][3], b0, b1);
            }
        }

        if (kc == 0) {
            // stage u[0..31][nt*128 .. +127] into smem (coalesced; readers at kc==31)
            #pragma unroll
            for (int t = 0; t < 16; t++) {
                int idx = tid + t * 256;
                int n = idx >> 7, el = idx & 127;
                su[n * SU_STRIDE + el] = g_u[n * EE + nt * 128 + el];
            }
        }

        if (kc == 31) {
            // epilogue: +u, tanh, *W3; fold into row partials; reset acc
            #pragma unroll
            for (int i = 0; i < 2; i++) {
                int r0 = mbase + i * 16 + g;
                int n0 = r0 & 31;
                int n1 = (r0 + 8) & 31;
                #pragma unroll
                for (int j = 0; j < 8; j++) {
                    int el = nbase + j * 8 + 2 * tg;
                    int e  = nt * 128 + el;
                    float w30 = __ldg(&W3[e]);
                    float w31 = __ldg(&W3[e + 1]);
                    float z00 = acc[i][j][0] + su[n0 * SU_STRIDE + el];
                    float z01 = acc[i][j][1] + su[n0 * SU_STRIDE + el + 1];
                    float z10 = acc[i][j][2] + su[n1 * SU_STRIDE + el];
                    float z11 = acc[i][j][3] + su[n1 * SU_STRIDE + el + 1];
                    pa[i * 2]     = fmaf(tanhf(z00), w30, pa[i * 2]);
                    pa[i * 2]     = fmaf(tanhf(z01), w31, pa[i * 2]);
                    pa[i * 2 + 1] = fmaf(tanhf(z10), w30, pa[i * 2 + 1]);
                    pa[i * 2 + 1] = fmaf(tanhf(z11), w31, pa[i * 2 + 1]);
                    acc[i][j][0] = acc[i][j][1] = acc[i][j][2] = acc[i][j][3] = 0.f;
                }
            }
        }

        __syncthreads();
        if (ls + 2 < NSTG) do_load(ls + 2);
    }

    // reduce pa over the 4 lanes of each group, then across the 2 n-warps
    #pragma unroll
    for (int i = 0; i < 2; i++)
        #pragma unroll
        for (int h = 0; h < 2; h++) {
            float v = pa[i * 2 + h];
            v += __shfl_xor_sync(0xffffffffu, v, 1);
            v += __shfl_xor_sync(0xffffffffu, v, 2);
            if (tg == 0) red[(mbase + i * 16 + h * 8 + g) * 2 + warp_n] = v;
        }
    __syncthreads();
    if (tid < 128) {
        int m = m0 + tid;
        float a = red[tid * 2] + red[tid * 2 + 1] + __ldg(&b3[0]);
        g_a[(m & 31) * SS + (m >> 5)] = a;
    }
}

// ============================================================================
// Kernel 3: softmax over S per column n
// ============================================================================
__global__ void k_softmax(float* __restrict__ alpha_out, int write_out) {
    int n = blockIdx.x;
    int tid = threadIdx.x;
    __shared__ float sred[256];
    const float* av = g_a + n * SS;

    float vals[8];
    float mx = -1e30f;
    #pragma unroll
    for (int i = 0; i < 8; i++) { vals[i] = av[tid + i * 256]; mx = fmaxf(mx, vals[i]); }
    sred[tid] = mx; __syncthreads();
    for (int o = 128; o; o >>= 1) { if (tid < o) sred[tid] = fmaxf(sred[tid], sred[tid + o]); __syncthreads(); }
    mx = sred[0]; __syncthreads();

    float lsum = 0.f;
    #pragma unroll
    for (int i = 0; i < 8; i++) { vals[i] = __expf(vals[i] - mx); lsum += vals[i]; }
    sred[tid] = lsum; __syncthreads();
    for (int o = 128; o; o >>= 1) { if (tid < o) sred[tid] += sred[tid + o]; __syncthreads(); }
    float inv = 1.f / sred[0];

    #pragma unroll
    for (int i = 0; i < 8; i++) {
        int s = tid + i * 256;
        float al = vals[i] * inv;
        g_alpha[n * SS + s] = al;
        if (write_out) alpha_out[s * NN + n] = al;
    }
}

// ============================================================================
// Kernel 4/5: context c[n][h] = sum_s alpha[s,n]*out_e[s,n,h]
// ============================================================================
__global__ void k_cpart(const float* __restrict__ X) {
    int chunk = blockIdx.x;   // 0..31
    int n     = blockIdx.y;   // 0..31
    int h0    = threadIdx.x * 4;
    float4 acc = make_float4(0.f, 0.f, 0.f, 0.f);
    int sbeg = chunk * (SS / 32);
    for (int s = sbeg; s < sbeg + (SS / 32); ++s) {
        float al = g_alpha[n * SS + s];
        float4 v = *(const float4*)(X + (size_t)(s * NN + n) * HH + h0);
        acc.x = fmaf(al, v.x, acc.x);
        acc.y = fmaf(al, v.y, acc.y);
        acc.z = fmaf(al, v.z, acc.z);
        acc.w = fmaf(al, v.w, acc.w);
    }
    *(float4*)(g_cpart + ((size_t)(chunk * NN + n) * HH) + h0) = acc;
}

__global__ void k_cfinal(float* __restrict__ cout) {
    int idx = blockIdx.x * 256 + threadIdx.x;   // 0 .. N*H-1
    float s = 0.f;
    #pragma unroll
    for (int ch = 0; ch < 32; ++ch) s += g_cpart[(size_t)ch * NN * HH + idx];
    cout[idx] = s;
}

// ============================================================================
extern "C" void kernel_launch(void* const* d_in, const int* in_sizes, int n_in,
                              void* d_out, int out_size) {
    const float* out_e  = (const float*)d_in[0];
    const float* hidden = (const float*)d_in[1];
    const float* W1     = (const float*)d_in[2];
    const float* b1     = (const float*)d_in[3];
    const float* W2     = (const float*)d_in[4];
    const float* b2     = (const float*)d_in[5];
    const float* W3     = (const float*)d_in[6];
    const float* b3     = (const float*)d_in[7];
    float* outp = (float*)d_out;

    k_u<<<(NN * EE) / 8, 256>>>(hidden, W1, b1, b2);

    const int smem_bytes = (3 * 128 * ASTRIDE * 2 + 32 * SU_STRIDE + 256) * 4;
    static int cfg_done = 0;
    if (!cfg_done) {
        cudaFuncSetAttribute(k_gemm, cudaFuncAttributeMaxDynamicSharedMemorySize, smem_bytes);
        cfg_done = 1;
    }
    k_gemm<<<MM / 128, 256, smem_bytes>>>(out_e, W2, W3, b3);

    int has_both   = (out_size >= NN * HH + SS * NN);
    int alpha_only = (!has_both && out_size == SS * NN);
    float* alpha_dst = has_both ? (outp + NN * HH) : (alpha_only ? outp : nullptr);

    k_softmax<<<NN, 256>>>(alpha_dst, alpha_dst != nullptr);

    if (!alpha_only) {
        dim3 g(32, NN);
        k_cpart<<<g, 256>>>(out_e);
        k_cfinal<<<(NN * HH) / 256, 256>>>(outp);
    }
}

// round 4
// speedup vs baseline: 5.2526x; 1.9152x over previous
#include <cuda_runtime.h>
#include <cuda_fp16.h>
#include <math.h>
#include <stdint.h>

#define SS 2048
#define NN 32
#define HH 1024
#define EE 1024
#define MM (SS*NN)   // 65536 rows

// ---- scratch (static __device__: no allocation in kernel_launch) ----
__device__ float  g_u[NN*EE];
__device__ float  g_a[NN*SS];
__device__ float  g_alpha[NN*SS];
__device__ float  g_cpart[32*NN*HH];
__device__ __half g_Xh[(size_t)MM*HH];   // fp16 copy of out_e (128MB)
__device__ __half g_W2h[(size_t)EE*HH];  // fp16 copy of W2 (2MB)

// ============================================================================
// PTX helpers (sm_80+ portable)
// ============================================================================
__device__ __forceinline__ uint32_t smem_u32(const void* p) {
    uint32_t a;
    asm("{ .reg .u64 t; cvta.to.shared.u64 t, %1; cvt.u32.u64 %0, t; }" : "=r"(a) : "l"(p));
    return a;
}
#define CP_ASYNC16(dst, src) \
    asm volatile("cp.async.cg.shared.global [%0], [%1], 16;" :: "r"(dst), "l"(src) : "memory")
#define CP_COMMIT() asm volatile("cp.async.commit_group;" ::: "memory")
#define CP_WAIT1()  asm volatile("cp.async.wait_group 1;" ::: "memory")
#define CP_WAIT0()  asm volatile("cp.async.wait_group 0;" ::: "memory")

#define LDSM_X4(r0, r1, r2, r3, addr) \
    asm volatile("ldmatrix.sync.aligned.m8n8.x4.shared.b16 {%0,%1,%2,%3}, [%4];" \
        : "=r"(r0), "=r"(r1), "=r"(r2), "=r"(r3) : "r"(addr))

__device__ __forceinline__ void mma_f16(float c[4],
                                        uint32_t a0, uint32_t a1, uint32_t a2, uint32_t a3,
                                        uint32_t b0, uint32_t b1) {
    asm volatile(
        "mma.sync.aligned.m16n8k16.row.col.f32.f16.f16.f32 "
        "{%0,%1,%2,%3}, {%4,%5,%6,%7}, {%8,%9}, {%0,%1,%2,%3};"
        : "+f"(c[0]), "+f"(c[1]), "+f"(c[2]), "+f"(c[3])
        : "r"(a0), "r"(a1), "r"(a2), "r"(a3), "r"(b0), "r"(b1));
}

// ============================================================================
// Kernel 0: fp32 -> fp16 conversion (vectorized float4 -> 2x half2)
// ============================================================================
__global__ void k_cvt(const float* __restrict__ src, __half* __restrict__ dst, int n4) {
    int i = blockIdx.x * blockDim.x + threadIdx.x;
    if (i >= n4) return;
    float4 v = ((const float4*)src)[i];
    __half2 lo = __floats2half2_rn(v.x, v.y);
    __half2 hi = __floats2half2_rn(v.z, v.w);
    uint2 w;
    w.x = *(uint32_t*)&lo;
    w.y = *(uint32_t*)&hi;
    ((uint2*)dst)[i] = w;
}

// ============================================================================
// Kernel 1: u[n][e] = hidden_d[n]·W1[e] + b1[e] + b2[e]   (one warp per dot)
// ============================================================================
__global__ void k_u(const float* __restrict__ hidden, const float* __restrict__ W1,
                    const float* __restrict__ b1, const float* __restrict__ b2) {
    int gw = (blockIdx.x * blockDim.x + threadIdx.x) >> 5;
    int lane = threadIdx.x & 31;
    if (gw >= NN * EE) return;
    int n = gw >> 10;
    int e = gw & (EE - 1);
    const float* hv = hidden + n * HH;
    const float* wv = W1 + (size_t)e * HH;
    float s = 0.f;
    #pragma unroll 4
    for (int h = lane; h < HH; h += 32) s = fmaf(hv[h], wv[h], s);
    #pragma unroll
    for (int o = 16; o; o >>= 1) s += __shfl_down_sync(0xffffffffu, s, o);
    if (lane == 0) g_u[n * EE + e] = s + b1[e] + b2[e];
}

// ============================================================================
// Kernel 2: fp16 mma.sync fused  X·W2ᵀ -> +u -> tanh -> ·W3 reduce -> a[m]
//   Block: 128 rows x full E (8 n-tiles of 128). 256 thr = 8 warps.
//   Warp tile 32x64. K-chunks of 64 halfs (128B rows), 3 smem buffers.
//   ldmatrix.x4 fragment loads, smem stride 72 halfs (conflict-free).
// ============================================================================
#define NSTG 128          // 8 n-tiles * 16 k-chunks
#define AST 72            // smem stride (halfs): 144B -> ldmatrix bank-free
#define TILE_B (128*AST*2)  // 18432 bytes per buffer per operand
#define SU_STRIDE 132

__global__ void __launch_bounds__(256, 1)
k_gemm(const float* __restrict__ W3, const float* __restrict__ b3) {
    extern __shared__ char smraw[];
    __half* As = (__half*)smraw;                        // 3*18432 B
    __half* Bs = (__half*)(smraw + 3 * TILE_B);         // 3*18432 B
    float*  su = (float*)(smraw + 6 * TILE_B);          // 32*132*4 B
    float* red = su + 32 * SU_STRIDE;                   // 128*2 floats

    const int tid = threadIdx.x;
    const int wid = tid >> 5;
    const int lid = tid & 31;
    const int g   = lid >> 2;
    const int tg  = lid & 3;
    const int warp_m = wid & 3;
    const int warp_n = wid >> 2;
    const int mbase = warp_m * 32;
    const int nbase = warp_n * 64;
    const int m0 = blockIdx.x * 128;

    const uint32_t sA = smem_u32(As);
    const uint32_t sB = smem_u32(Bs);

    // loader coords: 128 rows x 8 x 16B chunks per tile; 256 thr x 4 passes
    const int l_ch  = tid & 7;
    const int l_row = tid >> 3;   // 0..31

    const __half* Xh  = g_Xh;
    const __half* W2h = g_W2h;

    auto do_load = [&](int ls) {
        int nt  = ls >> 4;
        int kc  = ls & 15;
        int buf = ls - (ls / 3) * 3;
        const __half* gA = Xh  + (size_t)(m0 + l_row) * HH + kc * 64 + l_ch * 8;
        const __half* gB = W2h + (size_t)(nt * 128 + l_row) * HH + kc * 64 + l_ch * 8;
        uint32_t dA = sA + buf * TILE_B + l_row * (AST * 2) + l_ch * 16;
        uint32_t dB = sB + buf * TILE_B + l_row * (AST * 2) + l_ch * 16;
        #pragma unroll
        for (int t = 0; t < 4; t++) {
            CP_ASYNC16(dA, gA);
            CP_ASYNC16(dB, gB);
            gA += 32 * HH; gB += 32 * HH;
            dA += 32 * AST * 2; dB += 32 * AST * 2;
        }
        CP_COMMIT();
    };

    float acc[2][8][4];
    #pragma unroll
    for (int i = 0; i < 2; i++)
        #pragma unroll
        for (int j = 0; j < 8; j++)
            #pragma unroll
            for (int q = 0; q < 4; q++) acc[i][j][q] = 0.f;
    float pa[4] = {0.f, 0.f, 0.f, 0.f};

    // ldmatrix lane-address components (bytes)
    // A: row = mbase + i*16 + ((lid>>3)&1)*8 + (lid&7); koff = q*16 + (lid>>4)*8
    const int a_row_l = ((lid >> 3) & 1) * 8 + (lid & 7);
    const int a_koff_l = (lid >> 4) * 8;
    // B: n = nbase + j2*16 + ((lid>>4)&1)*8 + (lid&7); koff = q*16 + ((lid>>3)&1)*8
    const int b_row_l = ((lid >> 4) & 1) * 8 + (lid & 7);
    const int b_koff_l = ((lid >> 3) & 1) * 8;

    do_load(0);
    do_load(1);

    for (int ls = 0; ls < NSTG; ++ls) {
        int kc  = ls & 15;
        int nt  = ls >> 4;
        int buf = ls - (ls / 3) * 3;

        if (ls < NSTG - 1) { CP_WAIT1(); } else { CP_WAIT0(); }
        __syncthreads();

        const uint32_t Ab = sA + buf * TILE_B;
        const uint32_t Bb = sB + buf * TILE_B;

        #pragma unroll
        for (int q = 0; q < 4; q++) {
            uint32_t af[2][4];
            #pragma unroll
            for (int i = 0; i < 2; i++) {
                uint32_t addr = Ab + (mbase + i * 16 + a_row_l) * (AST * 2)
                              + (q * 16 + a_koff_l) * 2;
                LDSM_X4(af[i][0], af[i][1], af[i][2], af[i][3], addr);
            }
            #pragma unroll
            for (int j2 = 0; j2 < 4; j2++) {
                uint32_t b0, b1, b2, b3r;
                uint32_t addr = Bb + (nbase + j2 * 16 + b_row_l) * (AST * 2)
                              + (q * 16 + b_koff_l) * 2;
                LDSM_X4(b0, b1, b2, b3r, addr);
                mma_f16(acc[0][j2 * 2],     af[0][0], af[0][1], af[0][2], af[0][3], b0, b1);
                mma_f16(acc[1][j2 * 2],     af[1][0], af[1][1], af[1][2], af[1][3], b0, b1);
                mma_f16(acc[0][j2 * 2 + 1], af[0][0], af[0][1], af[0][2], af[0][3], b2, b3r);
                mma_f16(acc[1][j2 * 2 + 1], af[1][0], af[1][1], af[1][2], af[1][3], b2, b3r);
            }
        }

        if (kc == 0) {
            // stage u[0..31][nt*128 .. +127] into smem (readers at kc==15)
            #pragma unroll
            for (int t = 0; t < 16; t++) {
                int idx = tid + t * 256;
                int n = idx >> 7, el = idx & 127;
                su[n * SU_STRIDE + el] = g_u[n * EE + nt * 128 + el];
            }
        }

        if (kc == 15) {
            // epilogue: +u, tanh, *W3; fold into row partials; reset acc
            #pragma unroll
            for (int i = 0; i < 2; i++) {
                int r0 = mbase + i * 16 + g;
                int n0 = r0 & 31;
                int n1 = (r0 + 8) & 31;
                #pragma unroll
                for (int j = 0; j < 8; j++) {
                    int el = nbase + j * 8 + 2 * tg;
                    int e  = nt * 128 + el;
                    float w30 = __ldg(&W3[e]);
                    float w31 = __ldg(&W3[e + 1]);
                    float z00 = acc[i][j][0] + su[n0 * SU_STRIDE + el];
                    float z01 = acc[i][j][1] + su[n0 * SU_STRIDE + el + 1];
                    float z10 = acc[i][j][2] + su[n1 * SU_STRIDE + el];
                    float z11 = acc[i][j][3] + su[n1 * SU_STRIDE + el + 1];
                    pa[i * 2]     = fmaf(tanhf(z00), w30, pa[i * 2]);
                    pa[i * 2]     = fmaf(tanhf(z01), w31, pa[i * 2]);
                    pa[i * 2 + 1] = fmaf(tanhf(z10), w30, pa[i * 2 + 1]);
                    pa[i * 2 + 1] = fmaf(tanhf(z11), w31, pa[i * 2 + 1]);
                    acc[i][j][0] = acc[i][j][1] = acc[i][j][2] = acc[i][j][3] = 0.f;
                }
            }
        }

        __syncthreads();
        if (ls + 2 < NSTG) do_load(ls + 2);
    }

    // reduce pa over 4 lanes per group, then across the 2 n-warps
    #pragma unroll
    for (int i = 0; i < 2; i++)
        #pragma unroll
        for (int h = 0; h < 2; h++) {
            float v = pa[i * 2 + h];
            v += __shfl_xor_sync(0xffffffffu, v, 1);
            v += __shfl_xor_sync(0xffffffffu, v, 2);
            if (tg == 0) red[(mbase + i * 16 + h * 8 + g) * 2 + warp_n] = v;
        }
    __syncthreads();
    if (tid < 128) {
        int m = m0 + tid;
        float a = red[tid * 2] + red[tid * 2 + 1] + __ldg(&b3[0]);
        g_a[(m & 31) * SS + (m >> 5)] = a;
    }
}

// ============================================================================
// Kernel 3: softmax over S per column n
// ============================================================================
__global__ void k_softmax(float* __restrict__ alpha_out, int write_out) {
    int n = blockIdx.x;
    int tid = threadIdx.x;
    __shared__ float sred[256];
    const float* av = g_a + n * SS;

    float vals[8];
    float mx = -1e30f;
    #pragma unroll
    for (int i = 0; i < 8; i++) { vals[i] = av[tid + i * 256]; mx = fmaxf(mx, vals[i]); }
    sred[tid] = mx; __syncthreads();
    for (int o = 128; o; o >>= 1) { if (tid < o) sred[tid] = fmaxf(sred[tid], sred[tid + o]); __syncthreads(); }
    mx = sred[0]; __syncthreads();

    float lsum = 0.f;
    #pragma unroll
    for (int i = 0; i < 8; i++) { vals[i] = __expf(vals[i] - mx); lsum += vals[i]; }
    sred[tid] = lsum; __syncthreads();
    for (int o = 128; o; o >>= 1) { if (tid < o) sred[tid] += sred[tid + o]; __syncthreads(); }
    float inv = 1.f / sred[0];

    #pragma unroll
    for (int i = 0; i < 8; i++) {
        int s = tid + i * 256;
        float al = vals[i] * inv;
        g_alpha[n * SS + s] = al;
        if (write_out) alpha_out[s * NN + n] = al;
    }
}

// ============================================================================
// Kernel 4/5: context c[n][h] = sum_s alpha[s,n]*x[s,n,h]  (fp16 x, fp32 acc)
// ============================================================================
__global__ void k_cpart() {
    int chunk = blockIdx.x;   // 0..31
    int n     = blockIdx.y;   // 0..31
    int h0    = threadIdx.x * 4;
    float4 acc = make_float4(0.f, 0.f, 0.f, 0.f);
    int sbeg = chunk * (SS / 32);
    for (int s = sbeg; s < sbeg + (SS / 32); ++s) {
        float al = g_alpha[n * SS + s];
        uint2 raw = *(const uint2*)(g_Xh + (size_t)(s * NN + n) * HH + h0);
        __half2 hlo = *(__half2*)&raw.x;
        __half2 hhi = *(__half2*)&raw.y;
        float2 lo = __half22float2(hlo);
        float2 hi = __half22float2(hhi);
        acc.x = fmaf(al, lo.x, acc.x);
        acc.y = fmaf(al, lo.y, acc.y);
        acc.z = fmaf(al, hi.x, acc.z);
        acc.w = fmaf(al, hi.y, acc.w);
    }
    *(float4*)(g_cpart + ((size_t)(chunk * NN + n) * HH) + h0) = acc;
}

__global__ void k_cfinal(float* __restrict__ cout) {
    int idx = blockIdx.x * 256 + threadIdx.x;   // 0 .. N*H-1
    float s = 0.f;
    #pragma unroll
    for (int ch = 0; ch < 32; ++ch) s += g_cpart[(size_t)ch * NN * HH + idx];
    cout[idx] = s;
}

// ============================================================================
extern "C" void kernel_launch(void* const* d_in, const int* in_sizes, int n_in,
                              void* d_out, int out_size) {
    const float* out_e  = (const float*)d_in[0];
    const float* hidden = (const float*)d_in[1];
    const float* W1     = (const float*)d_in[2];
    const float* b1     = (const float*)d_in[3];
    const float* W2     = (const float*)d_in[4];
    const float* b2     = (const float*)d_in[5];
    const float* W3     = (const float*)d_in[6];
    const float* b3     = (const float*)d_in[7];
    float* outp = (float*)d_out;

    // fp32 -> fp16 copies
    __half *dXh = nullptr, *dW2h = nullptr;
    cudaGetSymbolAddress((void**)&dXh,  g_Xh);
    cudaGetSymbolAddress((void**)&dW2h, g_W2h);
    k_cvt<<<((size_t)MM * HH / 4 + 255) / 256, 256>>>(out_e, dXh, MM * (HH / 4));
    k_cvt<<<(EE * HH / 4 + 255) / 256, 256>>>(W2, dW2h, EE * HH / 4);

    k_u<<<(NN * EE) / 8, 256>>>(hidden, W1, b1, b2);

    const int smem_bytes = 6 * TILE_B + (32 * SU_STRIDE + 256) * 4;
    static int cfg_done = 0;
    if (!cfg_done) {
        cudaFuncSetAttribute(k_gemm, cudaFuncAttributeMaxDynamicSharedMemorySize, smem_bytes);
        cfg_done = 1;
    }
    k_gemm<<<MM / 128, 256, smem_bytes>>>(W3, b3);

    int has_both   = (out_size >= NN * HH + SS * NN);
    int alpha_only = (!has_both && out_size == SS * NN);
    float* alpha_dst = has_both ? (outp + NN * HH) : (alpha_only ? outp : nullptr);

    k_softmax<<<NN, 256>>>(alpha_dst, alpha_dst != nullptr);

    if (!alpha_only) {
        dim3 g(32, NN);
        k_cpart<<<g, 256>>>();
        k_cfinal<<<(NN * HH) / 256, 256>>>(outp);
    }
}

// round 7
// speedup vs baseline: 6.0372x; 1.1494x over previous
#include <cuda_runtime.h>
#include <cuda_fp16.h>
#include <math.h>
#include <stdint.h>

#define SS 2048
#define NN 32
#define HH 1024
#define EE 1024
#define MM (SS*NN)   // 65536 rows

// ---- scratch (static __device__: no allocation in kernel_launch) ----
__device__ float  g_u[NN*EE];
__device__ float  g_a[NN*SS];
__device__ float  g_alpha[NN*SS];
__device__ float  g_cpart[32*NN*HH];
__device__ __half g_Xh[(size_t)MM*HH];   // fp16 copy of out_e (128MB)
__device__ __half g_W2h[(size_t)EE*HH];  // fp16 copy of W2 (2MB)

// ============================================================================
// PTX helpers (sm_80+ portable)
// ============================================================================
__device__ __forceinline__ uint32_t smem_u32(const void* p) {
    uint32_t a;
    asm("{ .reg .u64 t; cvta.to.shared.u64 t, %1; cvt.u32.u64 %0, t; }" : "=r"(a) : "l"(p));
    return a;
}
#define CP_ASYNC16(dst, src) \
    asm volatile("cp.async.cg.shared.global [%0], [%1], 16;" :: "r"(dst), "l"(src) : "memory")
#define CP_COMMIT() asm volatile("cp.async.commit_group;" ::: "memory")
#define CP_WAIT1()  asm volatile("cp.async.wait_group 1;" ::: "memory")
#define CP_WAIT0()  asm volatile("cp.async.wait_group 0;" ::: "memory")

#define LDSM_X4(r0, r1, r2, r3, addr) \
    asm volatile("ldmatrix.sync.aligned.m8n8.x4.shared.b16 {%0,%1,%2,%3}, [%4];" \
        : "=r"(r0), "=r"(r1), "=r"(r2), "=r"(r3) : "r"(addr))

__device__ __forceinline__ void mma_f16(float c[4],
                                        uint32_t a0, uint32_t a1, uint32_t a2, uint32_t a3,
                                        uint32_t b0, uint32_t b1) {
    asm volatile(
        "mma.sync.aligned.m16n8k16.row.col.f32.f16.f16.f32 "
        "{%0,%1,%2,%3}, {%4,%5,%6,%7}, {%8,%9}, {%0,%1,%2,%3};"
        : "+f"(c[0]), "+f"(c[1]), "+f"(c[2]), "+f"(c[3])
        : "r"(a0), "r"(a1), "r"(a2), "r"(a3), "r"(b0), "r"(b1));
}

// ============================================================================
// Kernel 0: fp32 -> fp16 conversion
// ============================================================================
__global__ void k_cvt(const float* __restrict__ src, __half* __restrict__ dst, int n4) {
    int i = blockIdx.x * blockDim.x + threadIdx.x;
    if (i >= n4) return;
    float4 v = ((const float4*)src)[i];
    __half2 lo = __floats2half2_rn(v.x, v.y);
    __half2 hi = __floats2half2_rn(v.z, v.w);
    uint2 w;
    w.x = *(uint32_t*)&lo;
    w.y = *(uint32_t*)&hi;
    ((uint2*)dst)[i] = w;
}

// ============================================================================
// Kernel 1: u[n][e] = hidden_d[n]·W1[e] + b1[e] + b2[e]
// ============================================================================
__global__ void k_u(const float* __restrict__ hidden, const float* __restrict__ W1,
                    const float* __restrict__ b1, const float* __restrict__ b2) {
    int gw = (blockIdx.x * blockDim.x + threadIdx.x) >> 5;
    int lane = threadIdx.x & 31;
    if (gw >= NN * EE) return;
    int n = gw >> 10;
    int e = gw & (EE - 1);
    const float* hv = hidden + n * HH;
    const float* wv = W1 + (size_t)e * HH;
    float s = 0.f;
    #pragma unroll 4
    for (int h = lane; h < HH; h += 32) s = fmaf(hv[h], wv[h], s);
    #pragma unroll
    for (int o = 16; o; o >>= 1) s += __shfl_down_sync(0xffffffffu, s, o);
    if (lane == 0) g_u[n * EE + e] = s + b1[e] + b2[e];
}

// ============================================================================
// Kernel 2: fp16 mma.sync fused  X·W2ᵀ -> +u -> tanh -> ·W3 reduce -> a[m]
//   Block: 128 rows x 256 e-cols per n-tile (4 n-tiles for E=1024).
//   8 warps, warp tile 64x64 (2m x 4n). K-chunks of 64 halfs, 3 smem buffers.
// ============================================================================
#define NSTG 64           // 4 n-tiles * 16 k-chunks
#define AST 72            // smem stride (halfs)
#define A_TILE_B (128*AST*2)   // 18432 B
#define B_TILE_B (256*AST*2)   // 36864 B
#define NTILE 256
#define SU_STRIDE 264     // 256 + 8 pad (floats)

__global__ void __launch_bounds__(256, 1)
k_gemm(const float* __restrict__ W3, const float* __restrict__ b3) {
    extern __shared__ char smraw[];
    __half* As = (__half*)smraw;                                  // 3 * 18432 B
    __half* Bs = (__half*)(smraw + 3 * A_TILE_B);                 // 3 * 36864 B
    float*  su = (float*)(smraw + 3 * A_TILE_B + 3 * B_TILE_B);   // 32*264*4 B
    float* red = su + 32 * SU_STRIDE;                             // 128*4 floats

    const int tid = threadIdx.x;
    const int wid = tid >> 5;
    const int lid = tid & 31;
    const int g   = lid >> 2;
    const int tg  = lid & 3;
    const int warp_m = wid & 1;        // 2 m-warps of 64 rows
    const int warp_n = wid >> 1;       // 4 n-warps of 64 cols
    const int mbase = warp_m * 64;
    const int nbase = warp_n * 64;
    const int m0 = blockIdx.x * 128;

    const uint32_t sA = smem_u32(As);
    const uint32_t sB = smem_u32(Bs);

    const int l_ch  = tid & 7;         // 16B chunk within 128B row
    const int l_row = tid >> 3;        // 0..31

    const __half* Xh  = g_Xh;
    const __half* W2h = g_W2h;

    auto do_load = [&](int ls) {
        int nt  = ls >> 4;
        int kc  = ls & 15;
        int buf = ls - (ls / 3) * 3;
        const __half* gA = Xh  + (size_t)(m0 + l_row) * HH + kc * 64 + l_ch * 8;
        uint32_t dA = sA + buf * A_TILE_B + l_row * (AST * 2) + l_ch * 16;
        #pragma unroll
        for (int t = 0; t < 4; t++) {
            CP_ASYNC16(dA, gA);
            gA += 32 * HH;
            dA += 32 * AST * 2;
        }
        const __half* gB = W2h + (size_t)(nt * NTILE + l_row) * HH + kc * 64 + l_ch * 8;
        uint32_t dB = sB + buf * B_TILE_B + l_row * (AST * 2) + l_ch * 16;
        #pragma unroll
        for (int t = 0; t < 8; t++) {
            CP_ASYNC16(dB, gB);
            gB += 32 * HH;
            dB += 32 * AST * 2;
        }
        CP_COMMIT();
    };

    float acc[4][8][4];
    #pragma unroll
    for (int i = 0; i < 4; i++)
        #pragma unroll
        for (int j = 0; j < 8; j++)
            #pragma unroll
            for (int q = 0; q < 4; q++) acc[i][j][q] = 0.f;
    float pa[8];
    #pragma unroll
    for (int i = 0; i < 8; i++) pa[i] = 0.f;

    // ldmatrix lane-address components
    const int a_row_l  = ((lid >> 3) & 1) * 8 + (lid & 7);
    const int a_koff_l = (lid >> 4) * 8;
    const int b_row_l  = ((lid >> 4) & 1) * 8 + (lid & 7);
    const int b_koff_l = ((lid >> 3) & 1) * 8;

    do_load(0);
    do_load(1);

    for (int ls = 0; ls < NSTG; ++ls) {
        int kc  = ls & 15;
        int nt  = ls >> 4;
        int buf = ls - (ls / 3) * 3;

        if (ls < NSTG - 1) { CP_WAIT1(); } else { CP_WAIT0(); }
        __syncthreads();

        const uint32_t Ab = sA + buf * A_TILE_B;
        const uint32_t Bb = sB + buf * B_TILE_B;

        #pragma unroll
        for (int q = 0; q < 4; q++) {
            uint32_t af[4][4];
            #pragma unroll
            for (int i = 0; i < 4; i++) {
                uint32_t addr = Ab + (mbase + i * 16 + a_row_l) * (AST * 2)
                              + (q * 16 + a_koff_l) * 2;
                LDSM_X4(af[i][0], af[i][1], af[i][2], af[i][3], addr);
            }
            #pragma unroll
            for (int j2 = 0; j2 < 4; j2++) {
                uint32_t b0, b1, b2, b3r;
                uint32_t addr = Bb + (nbase + j2 * 16 + b_row_l) * (AST * 2)
                              + (q * 16 + b_koff_l) * 2;
                LDSM_X4(b0, b1, b2, b3r, addr);
                #pragma unroll
                for (int i = 0; i < 4; i++) {
                    mma_f16(acc[i][j2 * 2],     af[i][0], af[i][1], af[i][2], af[i][3], b0, b1);
                    mma_f16(acc[i][j2 * 2 + 1], af[i][0], af[i][1], af[i][2], af[i][3], b2, b3r);
                }
            }
        }

        if (kc == 0) {
            // stage u[0..31][nt*256 .. +255] into smem (readers at kc==15;
            // visibility via the __syncthreads at the end of this iteration)
            #pragma unroll
            for (int t = 0; t < 32; t++) {
                int idx = tid + t * 256;
                int n = idx >> 8, el = idx & 255;
                su[n * SU_STRIDE + el] = g_u[n * EE + nt * NTILE + el];
            }
        }

        if (kc == 15) {
            // epilogue: +u, tanh, *W3; fold into row partials; reset acc
            #pragma unroll
            for (int i = 0; i < 4; i++) {
                int r0 = mbase + i * 16 + g;
                int n0 = r0 & 31;
                int n1 = (r0 + 8) & 31;
                #pragma unroll
                for (int j = 0; j < 8; j++) {
                    int el = nbase + j * 8 + 2 * tg;
                    int e  = nt * NTILE + el;
                    float w30 = __ldg(&W3[e]);
                    float w31 = __ldg(&W3[e + 1]);
                    float z00 = acc[i][j][0] + su[n0 * SU_STRIDE + el];
                    float z01 = acc[i][j][1] + su[n0 * SU_STRIDE + el + 1];
                    float z10 = acc[i][j][2] + su[n1 * SU_STRIDE + el];
                    float z11 = acc[i][j][3] + su[n1 * SU_STRIDE + el + 1];
                    pa[i * 2]     = fmaf(tanhf(z00), w30, pa[i * 2]);
                    pa[i * 2]     = fmaf(tanhf(z01), w31, pa[i * 2]);
                    pa[i * 2 + 1] = fmaf(tanhf(z10), w30, pa[i * 2 + 1]);
                    pa[i * 2 + 1] = fmaf(tanhf(z11), w31, pa[i * 2 + 1]);
                    acc[i][j][0] = acc[i][j][1] = acc[i][j][2] = acc[i][j][3] = 0.f;
                }
            }
        }

        __syncthreads();
        if (ls + 2 < NSTG) do_load(ls + 2);
    }

    // reduce pa over 4 lanes of each group, then across the 4 n-warps
    #pragma unroll
    for (int i = 0; i < 4; i++)
        #pragma unroll
        for (int h = 0; h < 2; h++) {
            float v = pa[i * 2 + h];
            v += __shfl_xor_sync(0xffffffffu, v, 1);
            v += __shfl_xor_sync(0xffffffffu, v, 2);
            if (tg == 0) red[(mbase + i * 16 + h * 8 + g) * 4 + warp_n] = v;
        }
    __syncthreads();
    if (tid < 128) {
        int m = m0 + tid;
        float a = red[tid * 4] + red[tid * 4 + 1] + red[tid * 4 + 2] + red[tid * 4 + 3]
                + __ldg(&b3[0]);
        g_a[(m & 31) * SS + (m >> 5)] = a;
    }
}

// ============================================================================
// Kernel 3: softmax over S per column n
// ============================================================================
__global__ void k_softmax(float* __restrict__ alpha_out, int write_out) {
    int n = blockIdx.x;
    int tid = threadIdx.x;
    __shared__ float sred[256];
    const float* av = g_a + n * SS;

    float vals[8];
    float mx = -1e30f;
    #pragma unroll
    for (int i = 0; i < 8; i++) { vals[i] = av[tid + i * 256]; mx = fmaxf(mx, vals[i]); }
    sred[tid] = mx; __syncthreads();
    for (int o = 128; o; o >>= 1) { if (tid < o) sred[tid] = fmaxf(sred[tid], sred[tid + o]); __syncthreads(); }
    mx = sred[0]; __syncthreads();

    float lsum = 0.f;
    #pragma unroll
    for (int i = 0; i < 8; i++) { vals[i] = __expf(vals[i] - mx); lsum += vals[i]; }
    sred[tid] = lsum; __syncthreads();
    for (int o = 128; o; o >>= 1) { if (tid < o) sred[tid] += sred[tid + o]; __syncthreads(); }
    float inv = 1.f / sred[0];

    #pragma unroll
    for (int i = 0; i < 8; i++) {
        int s = tid + i * 256;
        float al = vals[i] * inv;
        g_alpha[n * SS + s] = al;
        if (write_out) alpha_out[s * NN + n] = al;
    }
}

// ============================================================================
// Kernel 4/5: context c[n][h] = sum_s alpha[s,n]*x[s,n,h]  (fp16 x, fp32 acc)
// ============================================================================
__global__ void k_cpart() {
    int chunk = blockIdx.x;   // 0..31
    int n     = blockIdx.y;   // 0..31
    int h0    = threadIdx.x * 4;
    float4 acc = make_float4(0.f, 0.f, 0.f, 0.f);
    int sbeg = chunk * (SS / 32);
    for (int s = sbeg; s < sbeg + (SS / 32); ++s) {
        float al = g_alpha[n * SS + s];
        uint2 raw = *(const uint2*)(g_Xh + (size_t)(s * NN + n) * HH + h0);
        __half2 hlo = *(__half2*)&raw.x;
        __half2 hhi = *(__half2*)&raw.y;
        float2 lo = __half22float2(hlo);
        float2 hi = __half22float2(hhi);
        acc.x = fmaf(al, lo.x, acc.x);
        acc.y = fmaf(al, lo.y, acc.y);
        acc.z = fmaf(al, hi.x, acc.z);
        acc.w = fmaf(al, hi.y, acc.w);
    }
    *(float4*)(g_cpart + ((size_t)(chunk * NN + n) * HH) + h0) = acc;
}

__global__ void k_cfinal(float* __restrict__ cout) {
    int idx = blockIdx.x * 256 + threadIdx.x;   // 0 .. N*H-1
    float s = 0.f;
    #pragma unroll
    for (int ch = 0; ch < 32; ++ch) s += g_cpart[(size_t)ch * NN * HH + idx];
    cout[idx] = s;
}

// ============================================================================
extern "C" void kernel_launch(void* const* d_in, const int* in_sizes, int n_in,
                              void* d_out, int out_size) {
    const float* out_e  = (const float*)d_in[0];
    const float* hidden = (const float*)d_in[1];
    const float* W1     = (const float*)d_in[2];
    const float* b1     = (const float*)d_in[3];
    const float* W2     = (const float*)d_in[4];
    const float* b2     = (const float*)d_in[5];
    const float* W3     = (const float*)d_in[6];
    const float* b3     = (const float*)d_in[7];
    float* outp = (float*)d_out;

    __half *dXh = nullptr, *dW2h = nullptr;
    cudaGetSymbolAddress((void**)&dXh,  g_Xh);
    cudaGetSymbolAddress((void**)&dW2h, g_W2h);
    k_cvt<<<((size_t)MM * HH / 4 + 255) / 256, 256>>>(out_e, dXh, MM * (HH / 4));
    k_cvt<<<(EE * HH / 4 + 255) / 256, 256>>>(W2, dW2h, EE * HH / 4);

    k_u<<<(NN * EE) / 8, 256>>>(hidden, W1, b1, b2);

    const int smem_bytes = 3 * A_TILE_B + 3 * B_TILE_B + (32 * SU_STRIDE + 128 * 4) * 4;
    static int cfg_done = 0;
    if (!cfg_done) {
        cudaFuncSetAttribute(k_gemm, cudaFuncAttributeMaxDynamicSharedMemorySize, smem_bytes);
        cfg_done = 1;
    }
    k_gemm<<<MM / 128, 256, smem_bytes>>>(W3, b3);

    int has_both   = (out_size >= NN * HH + SS * NN);
    int alpha_only = (!has_both && out_size == SS * NN);
    float* alpha_dst = has_both ? (outp + NN * HH) : (alpha_only ? outp : nullptr);

    k_softmax<<<NN, 256>>>(alpha_dst, alpha_dst != nullptr);

    if (!alpha_only) {
        dim3 g(32, NN);
        k_cpart<<<g, 256>>>();
        k_cfinal<<<(NN * HH) / 256, 256>>>(outp);
    }
}